// round 9
// baseline (speedup 1.0000x reference)
#include <cuda_runtime.h>
#include <cuda_fp16.h>
#include <math.h>
#include <stdint.h>

// N = 64*32*32 = 65536 rows, D = 256, K = 1024
// Output layout: [loss (1), q_out (16777216), perplexity (1)]

#define NROWS   65536
#define DDIM    256
#define KCODES  1024
#define BATCH   64
#define HWSZ    1024
#define QELEMS  16777216

#define NEG_INF (-__int_as_float(0x7f800000))
#define JAX_PARTITIONABLE 1

// ---------------- scratch (device globals; no allocation allowed) ----------------
__device__ __half g_Xh[(size_t)NROWS * DDIM];          // fp16(x)         (32 MB)
__device__ __half g_Eh[(size_t)KCODES * DDIM];         // fp16(e)
__device__ float g_S[(size_t)NROWS * KCODES];          // logits          (256 MB)
__device__ float g_bnorm[KCODES];
__device__ float g_counts[KCODES];
__device__ float g_entrow[NROWS];
__device__ int   g_idx[NROWS];

// ---------------- helpers ----------------
__device__ __forceinline__ uint32_t smem_u32(const void* p) {
    uint32_t a;
    asm("{ .reg .u64 t; cvta.to.shared.u64 t, %1; cvt.u32.u64 %0, t; }" : "=r"(a) : "l"(p));
    return a;
}
__device__ __forceinline__ void ldsm4(uint32_t* r, const void* p) {
    uint32_t addr = smem_u32(p);
    asm volatile("ldmatrix.sync.aligned.m8n8.x4.shared.b16 {%0,%1,%2,%3}, [%4];"
        : "=r"(r[0]), "=r"(r[1]), "=r"(r[2]), "=r"(r[3]) : "r"(addr));
}
__device__ __forceinline__ void mma_f16(float* c, const uint32_t* a, uint32_t b0, uint32_t b1) {
    asm("mma.sync.aligned.m16n8k16.row.col.f32.f16.f16.f32 "
        "{%0,%1,%2,%3}, {%4,%5,%6,%7}, {%8,%9}, {%0,%1,%2,%3};"
        : "+f"(c[0]), "+f"(c[1]), "+f"(c[2]), "+f"(c[3])
        : "r"(a[0]), "r"(a[1]), "r"(a[2]), "r"(a[3]), "r"(b0), "r"(b1));
}
__device__ __forceinline__ void cpa16(uint32_t s, const void* g) {
    asm volatile("cp.async.ca.shared.global [%0], [%1], 16;" :: "r"(s), "l"(g));
}
#define CPA_COMMIT() asm volatile("cp.async.commit_group;" ::: "memory")
#define CPA_WAIT2()  asm volatile("cp.async.wait_group 2;" ::: "memory")

// ---------------- threefry2x32 (JAX-exact, validated R4/R6/R7/R8) ----------------
__device__ __forceinline__ void threefry2x32(unsigned int x0, unsigned int x1,
                                             unsigned int& r0, unsigned int& r1) {
    const unsigned int k0 = 0u, k1 = 42u;
    const unsigned int k2 = 0u ^ 42u ^ 0x1BD11BDAu;
#define TFR(r) { x0 += x1; x1 = __funnelshift_l(x1, x1, r); x1 ^= x0; }
    x0 += k0; x1 += k1;
    TFR(13) TFR(15) TFR(26) TFR(6)
    x0 += k1; x1 += k2 + 1u;
    TFR(17) TFR(29) TFR(16) TFR(24)
    x0 += k2; x1 += k0 + 2u;
    TFR(13) TFR(15) TFR(26) TFR(6)
    x0 += k0; x1 += k1 + 3u;
    TFR(17) TFR(29) TFR(16) TFR(24)
    x0 += k1; x1 += k2 + 4u;
    TFR(13) TFR(15) TFR(26) TFR(6)
    x0 += k2; x1 += k0 + 5u;
#undef TFR
    r0 = x0; r1 = x1;
}
__device__ __forceinline__ unsigned int rbits_at(unsigned int e) {
#if JAX_PARTITIONABLE
    unsigned int r0, r1;
    threefry2x32(0u, e, r0, r1);
    return r0 ^ r1;
#else
    const unsigned int NH = (NROWS * (unsigned)KCODES) / 2u;
    unsigned int p = (e < NH) ? e : (e - NH);
    unsigned int r0, r1;
    threefry2x32(p, p + NH, r0, r1);
    return (e < NH) ? r0 : r1;
#endif
}
// exact version: reference-grade (used in refinement; matched reference 4 rounds)
__device__ __forceinline__ float gumbel_exact(unsigned int e) {
    unsigned int bits = rbits_at(e);
    float f = __uint_as_float((bits >> 9) | 0x3f800000u) - 1.0f;
    float u = fmaxf(1e-9f, f + 1e-9f);
    return -logf(-logf(u));
}
// fast version: used only for the scan; noise (<1e-4 abs) covered by the
// exact fp64 top-2 refinement (threshold 1e-2).
__device__ __forceinline__ float gumbel_fast(unsigned int e) {
    unsigned int bits = rbits_at(e);
    float f = __uint_as_float((bits >> 9) | 0x3f800000u) - 1.0f;
    float u = fmaxf(1e-9f, f + 1e-9f);
    float v;
    if (f > 0.996f) v = -logf(u);     // near u=1: cancellation -> exact (rare)
    else            v = -__logf(u);
    return -__logf(v);
}

// ---------------- kernel 0: zero counts ----------------
__global__ void zero_kernel() {
    int t = threadIdx.x;
    if (t < KCODES) g_counts[t] = 0.0f;
}

// ---------------- kernel 1: transpose + fp16 convert ----------------
__global__ void transpose_kernel(const float* __restrict__ in) {
    __shared__ float tile[32][33];
    int b   = blockIdx.z;
    int hw0 = blockIdx.x * 32;
    int d0  = blockIdx.y * 32;
    int tx = threadIdx.x, ty = threadIdx.y;
    const float* src = in + (size_t)b * (DDIM * HWSZ);
#pragma unroll
    for (int j = 0; j < 4; j++) {
        int d  = d0 + ty + j * 8;
        int hw = hw0 + tx;
        tile[ty + j * 8][tx] = src[(size_t)d * HWSZ + hw];
    }
    __syncthreads();
#pragma unroll
    for (int j = 0; j < 4; j++) {
        int hw = hw0 + ty + j * 8;
        int d  = d0 + tx;
        g_Xh[(size_t)(b * HWSZ + hw) * DDIM + d] = __float2half_rn(tile[tx][ty + j * 8]);
    }
}

// ---------------- kernel 2: embedding norms + fp16 convert ----------------
__global__ void prep_e_kernel(const float* __restrict__ E) {
    __shared__ float red[256];
    int k = blockIdx.x, t = threadIdx.x;
    float v = E[(size_t)k * DDIM + t];
    g_Eh[(size_t)k * DDIM + t] = __float2half_rn(v);
    red[t] = v * v;
    __syncthreads();
    for (int off = 128; off > 0; off >>= 1) {
        if (t < off) red[t] += red[t + off];
        __syncthreads();
    }
    if (t == 0) g_bnorm[k] = red[0];
}

// ---------------- kernel 3: fp16 mma.sync GEMM, cp.async 4-stage, 2 CTA/SM ----------------
#define LDS_ROW 40                                  // fp16 elems per smem row (80B)
#define TILE_ELEMS (128 * LDS_ROW)
#define TILE_BYTES (TILE_ELEMS * 2)                 // 10240
#define NSTAGE 4
#define SMEM_DYN (512 + NSTAGE * 2 * TILE_BYTES)    // 512 + 81920 = 82432

__device__ __forceinline__ void issue_stage(uint32_t s_tiles_u32, int buf, int m0, int n0, int d0) {
    int tid = threadIdx.x;
    uint32_t base = s_tiles_u32 + (uint32_t)buf * 2 * TILE_BYTES;
#pragma unroll
    for (int q = 0; q < 2; q++) {
        int idx = tid + 256 * q;
        int row = idx >> 2, quad = idx & 3;
        uint32_t soff = (uint32_t)(row * LDS_ROW + quad * 8) * 2;
        size_t ga = (size_t)(m0 + row) * DDIM + d0 + quad * 8;
        size_t gb = (size_t)(n0 + row) * DDIM + d0 + quad * 8;
        cpa16(base + 0 * TILE_BYTES + soff, g_Xh + ga);
        cpa16(base + 1 * TILE_BYTES + soff, g_Eh + gb);
    }
}

__global__ __launch_bounds__(256, 2) void gemm_f16_kernel() {
    extern __shared__ char smem[];
    float* s_bn = (float*)smem;
    __half* s_tiles = (__half*)(smem + 512);
    uint32_t s_tiles_u32 = smem_u32(s_tiles);
#define TILE_PTR(st, a) (s_tiles + ((st) * 2 + (a)) * TILE_ELEMS)

    int tid = threadIdx.x, wid = tid >> 5, lane = tid & 31;
    int warp_m = wid & 3, warp_n = wid >> 2;
    int n0 = blockIdx.x * 128;
    int m0 = blockIdx.y * 128;

    if (tid < 128) s_bn[tid] = g_bnorm[n0 + tid];

    float acc[2][8][4];
#pragma unroll
    for (int i = 0; i < 2; i++)
#pragma unroll
        for (int j = 0; j < 8; j++)
#pragma unroll
            for (int q = 0; q < 4; q++) acc[i][j][q] = 0.0f;

    issue_stage(s_tiles_u32, 0, m0, n0, 0);
    CPA_COMMIT();
    issue_stage(s_tiles_u32, 1, m0, n0, 32);
    CPA_COMMIT();
    issue_stage(s_tiles_u32, 2, m0, n0, 64);
    CPA_COMMIT();

    int a_row = warp_m * 32 + (lane & 15);
    int b_row = warp_n * 64 + (lane & 15);
    int k_off = (lane >> 4) * 8;

    for (int c = 0; c < 8; c++) {
        CPA_WAIT2();           // stage c landed (c+1, c+2 may fly)
        __syncthreads();       // all warps done reading buf (c+3)%4
        if (c + 3 < 8) {
            issue_stage(s_tiles_u32, (c + 3) % NSTAGE, m0, n0, (c + 3) * 32);
            CPA_COMMIT();
        }
        int st = c % NSTAGE;
        const __half* At = TILE_PTR(st, 0);
        const __half* Bt = TILE_PTR(st, 1);
#pragma unroll
        for (int ks = 0; ks < 2; ks++) {
            int kc = ks * 16 + k_off;
            uint32_t fA[2][4];
#pragma unroll
            for (int mt = 0; mt < 2; mt++)
                ldsm4(fA[mt], At + (a_row + mt * 16) * LDS_ROW + kc);
#pragma unroll
            for (int bt = 0; bt < 4; bt++) {
                uint32_t fB[4];
                ldsm4(fB, Bt + (b_row + bt * 16) * LDS_ROW + kc);
                mma_f16(acc[0][2 * bt],     fA[0], fB[0], fB[2]);
                mma_f16(acc[1][2 * bt],     fA[1], fB[0], fB[2]);
                mma_f16(acc[0][2 * bt + 1], fA[0], fB[1], fB[3]);
                mma_f16(acc[1][2 * bt + 1], fA[1], fB[1], fB[3]);
            }
        }
    }

    // epilogue: s = 2*acc - bnorm
    int g = lane >> 2, tg = lane & 3;
#pragma unroll
    for (int mi = 0; mi < 2; mi++) {
        int r0 = m0 + warp_m * 32 + mi * 16 + g;
#pragma unroll
        for (int ni = 0; ni < 8; ni++) {
            int cl = warp_n * 64 + ni * 8 + tg * 2;
            float bn0 = s_bn[cl], bn1 = s_bn[cl + 1];
            float2 o0 = { fmaf(2.0f, acc[mi][ni][0], -bn0), fmaf(2.0f, acc[mi][ni][1], -bn1) };
            float2 o1 = { fmaf(2.0f, acc[mi][ni][2], -bn0), fmaf(2.0f, acc[mi][ni][3], -bn1) };
            *(float2*)&g_S[(size_t)r0 * KCODES + n0 + cl] = o0;
            *(float2*)&g_S[(size_t)(r0 + 8) * KCODES + n0 + cl] = o1;
        }
    }
#undef TILE_PTR
}

// ---------------- top-2 merge helper ----------------
__device__ __forceinline__ void top2_merge(float& v1, int& i1, float& v2, int& i2,
                                           float b1, int bi1, float b2, int bi2) {
    bool bwin = (b1 > v1) || (b1 == v1 && bi1 < i1);
    if (bwin) {
        bool aw = (v1 > b2) || (v1 == b2 && i1 < bi2);
        v2 = aw ? v1 : b2; i2 = aw ? i1 : bi2;
        v1 = b1; i1 = bi1;
    } else {
        bool bw = (b1 > v2) || (b1 == v2 && bi1 < i2);
        if (bw) { v2 = b1; i2 = bi1; }
    }
}

// ---------------- kernel 4: per-row softmax-entropy + gumbel top-2 argmax ----------------
__global__ __launch_bounds__(256)
void epi_kernel(const float* __restrict__ inp, const float* __restrict__ emb) {
    int n = blockIdx.x;
    int t = threadIdx.x;
    int lane = t & 31, wid = t >> 5;
    const float* srow = g_S + (size_t)n * KCODES;

    float4 s4 = ((const float4*)srow)[t];
    float svv[4] = {s4.x, s4.y, s4.z, s4.w};

    float v1 = NEG_INF, v2 = NEG_INF;
    int   i1 = 0x7FFFFFFF, i2 = 0x7FFFFFFF;
    float smax = NEG_INF;
#pragma unroll
    for (int jj = 0; jj < 4; jj++) {
        int k = t * 4 + jj;
        float y = svv[jj] + gumbel_fast((unsigned)n * (unsigned)KCODES + (unsigned)k);
        if (y > v1 || (y == v1 && k < i1)) { v2 = v1; i2 = i1; v1 = y; i1 = k; }
        else if (y > v2 || (y == v2 && k < i2)) { v2 = y; i2 = k; }
        smax = fmaxf(smax, svv[jj]);
    }

    // warp-level top-2 + max reduction
#pragma unroll
    for (int off = 16; off > 0; off >>= 1) {
        float b1 = __shfl_down_sync(0xFFFFFFFFu, v1, off);
        int  bi1 = __shfl_down_sync(0xFFFFFFFFu, i1, off);
        float b2 = __shfl_down_sync(0xFFFFFFFFu, v2, off);
        int  bi2 = __shfl_down_sync(0xFFFFFFFFu, i2, off);
        smax = fmaxf(smax, __shfl_down_sync(0xFFFFFFFFu, smax, off));
        top2_merge(v1, i1, v2, i2, b1, bi1, b2, bi2);
    }

    __shared__ float wv1[8]; __shared__ int wi1[8];
    __shared__ float wv2[8]; __shared__ int wi2[8];
    __shared__ float wmx[8];
    __shared__ float wz[8];  __shared__ float ww[8];
    __shared__ int   s_bi, s_bi2;
    __shared__ float s_gap, s_max;
    __shared__ double rd1[256]; __shared__ double rd2[256];

    if (lane == 0) { wv1[wid] = v1; wi1[wid] = i1; wv2[wid] = v2; wi2[wid] = i2; wmx[wid] = smax; }
    __syncthreads();

    if (wid == 0) {
        float a1 = (lane < 8) ? wv1[lane] : NEG_INF;
        int  ai1 = (lane < 8) ? wi1[lane] : 0x7FFFFFFF;
        float a2 = (lane < 8) ? wv2[lane] : NEG_INF;
        int  ai2 = (lane < 8) ? wi2[lane] : 0x7FFFFFFF;
        float mx = (lane < 8) ? wmx[lane] : NEG_INF;
#pragma unroll
        for (int off = 4; off > 0; off >>= 1) {
            float b1 = __shfl_down_sync(0xFFFFFFFFu, a1, off);
            int  bi1 = __shfl_down_sync(0xFFFFFFFFu, ai1, off);
            float b2 = __shfl_down_sync(0xFFFFFFFFu, a2, off);
            int  bi2 = __shfl_down_sync(0xFFFFFFFFu, ai2, off);
            mx = fmaxf(mx, __shfl_down_sync(0xFFFFFFFFu, mx, off));
            top2_merge(a1, ai1, a2, ai2, b1, bi1, b2, bi2);
        }
        if (lane == 0) { s_bi = ai1; s_bi2 = ai2; s_gap = a1 - a2; s_max = mx; }
    }
    __syncthreads();

    int bidx = s_bi;
    // block-parallel fp64 + exact-gumbel refinement for near ties
    if (s_gap < 1e-2f) {
        int b = n >> 10, hw = n & 1023;
        float xd = inp[(size_t)b * (DDIM * HWSZ) + (size_t)t * HWSZ + hw];
        float e1 = emb[(size_t)s_bi  * DDIM + t];
        float e2 = emb[(size_t)s_bi2 * DDIM + t];
        rd1[t] = 2.0 * (double)xd * (double)e1 - (double)e1 * (double)e1;
        rd2[t] = 2.0 * (double)xd * (double)e2 - (double)e2 * (double)e2;
        __syncthreads();
        for (int off = 128; off > 0; off >>= 1) {
            if (t < off) { rd1[t] += rd1[t + off]; rd2[t] += rd2[t + off]; }
            __syncthreads();
        }
        if (t == 0) {
            double y1 = rd1[0] + (double)gumbel_exact((unsigned)n * (unsigned)KCODES + (unsigned)s_bi);
            double y2 = rd2[0] + (double)gumbel_exact((unsigned)n * (unsigned)KCODES + (unsigned)s_bi2);
            if (y2 > y1 || (y2 == y1 && s_bi2 < s_bi)) bidx = s_bi2;
        }
        __syncthreads();
    }

    float mrow = s_max;
    float z = 0.0f, w = 0.0f;
#pragma unroll
    for (int jj = 0; jj < 4; jj++) {
        float d = svv[jj] - mrow;
        float e = __expf(d);
        z += e;
        w += d * e;
    }
#pragma unroll
    for (int off = 16; off > 0; off >>= 1) {
        z += __shfl_down_sync(0xFFFFFFFFu, z, off);
        w += __shfl_down_sync(0xFFFFFFFFu, w, off);
    }
    if (lane == 0) { wz[wid] = z; ww[wid] = w; }
    __syncthreads();
    if (t == 0) {
        float Z = 0.0f, W = 0.0f;
#pragma unroll
        for (int q = 0; q < 8; q++) { Z += wz[q]; W += ww[q]; }
        g_entrow[n] = W / Z - logf(Z);
        g_idx[n] = bidx;
        atomicAdd(&g_counts[bidx], 1.0f);
    }
}

// ---------------- kernel 5: scatter q_out = embedding[idx] ----------------
__global__ __launch_bounds__(256)
void scatter_kernel(const float* __restrict__ E, float* __restrict__ qout) {
    int b  = blockIdx.y;
    int hw = blockIdx.x * 256 + threadIdx.x;
    int n  = b * HWSZ + hw;
    int row = g_idx[n];
    const float4* e4 = reinterpret_cast<const float4*>(E + (size_t)row * DDIM);
    float* outb = qout + (size_t)b * (DDIM * HWSZ) + hw;
#pragma unroll 4
    for (int d4 = 0; d4 < DDIM / 4; d4++) {
        float4 v = e4[d4];
        outb[(size_t)(d4 * 4 + 0) * HWSZ] = v.x;
        outb[(size_t)(d4 * 4 + 1) * HWSZ] = v.y;
        outb[(size_t)(d4 * 4 + 2) * HWSZ] = v.z;
        outb[(size_t)(d4 * 4 + 3) * HWSZ] = v.w;
    }
}

// ---------------- kernel 6: finalize ----------------
__global__ __launch_bounds__(1024)
void finalize_kernel(float* __restrict__ out) {
    __shared__ double sh1[1024];
    __shared__ double sh2[1024];
    int t = threadIdx.x;
    double es = 0.0;
    for (int j = 0; j < NROWS / 1024; j++) es += (double)g_entrow[t + 1024 * j];
    float c = g_counts[t];
    float q = c * (1.0f / (float)NROWS);
    float term = q * logf(q + 1e-10f);
    sh1[t] = es;
    sh2[t] = (double)term;
    __syncthreads();
    for (int off = 512; off > 0; off >>= 1) {
        if (t < off) { sh1[t] += sh1[t + off]; sh2[t] += sh2[t + off]; }
        __syncthreads();
    }
    if (t == 0) {
        out[0] = 0.25f * (float)(sh1[0] / (double)NROWS);
        out[1 + QELEMS] = expf(-(float)sh2[0]);
    }
}

// ---------------- launch ----------------
extern "C" void kernel_launch(void* const* d_in, const int* in_sizes, int n_in,
                              void* d_out, int out_size) {
    const float* inp = (const float*)d_in[0];
    const float* emb = (const float*)d_in[1];
    float* out = (float*)d_out;

    cudaFuncSetAttribute(gemm_f16_kernel, cudaFuncAttributeMaxDynamicSharedMemorySize, SMEM_DYN);

    zero_kernel<<<1, 1024>>>();
    transpose_kernel<<<dim3(HWSZ / 32, DDIM / 32, BATCH), dim3(32, 8)>>>(inp);
    prep_e_kernel<<<KCODES, 256>>>(emb);
    gemm_f16_kernel<<<dim3(KCODES / 128, NROWS / 128), 256, SMEM_DYN>>>();
    epi_kernel<<<NROWS, 256>>>(inp, emb);
    scatter_kernel<<<dim3(HWSZ / 256, BATCH), 256>>>(emb, out + 1);
    finalize_kernel<<<1, 1024>>>(out);
}